// round 15
// baseline (speedup 1.0000x reference)
#include <cuda_runtime.h>
#include <cuda_bf16.h>
#include <math.h>
#include <stdint.h>

#define NN  50000
#define NE  800000
#define FIN 128
#define HID 256
#define NG  128

#define SCAN_SPAN 1024
#define SCAN_NB   ((NN + SCAN_SPAN - 1) / SCAN_SPAN)   // 49

// ---------------- scratch (static device globals; no allocation) ----------------
__device__ int   g_deg[NN];        // ZERO at entry of every call (static-zero first call;
                                   // re-zeroed by k_scanC each call after last read)
__device__ float g_dinv[NN];
__device__ int   g_rowptr[NN + 1];
__device__ int   g_cur[NN + 1];
__device__ int   g_col[NE];
__device__ int   g_bsum[SCAN_NB];
__device__ __nv_bfloat16 g_xbf [(size_t)NN * FIN];
__device__ __nv_bfloat16 g_agg1[(size_t)NN * FIN];
__device__ __nv_bfloat16 g_h1  [(size_t)NN * HID];
__device__ __nv_bfloat16 g_agg2[(size_t)NN * HID];
__device__ __nv_bfloat16 g_h2  [(size_t)NN * HID];
__device__ float g_pool[NG * HID];
__device__ int   g_gs[NG + 1];

__device__ __forceinline__ uint32_t packbf(float lo, float hi) {
    __nv_bfloat162 t = __floats2bfloat162_rn(lo, hi);
    return *reinterpret_cast<uint32_t*>(&t);
}
// exact bf16 -> f32 widening via bit ops (SHF/LOP3, lat 4, alu pipe; no CVT)
__device__ __forceinline__ float bflo(uint32_t u) { return __int_as_float(u << 16); }
__device__ __forceinline__ float bfhi(uint32_t u) { return __int_as_float(u & 0xFFFF0000u); }

// ---------------- fused: edge histogram (into zeroed g_deg) + x->bf16 ----------------
__global__ void k_histinit(const float* __restrict__ x, const int* __restrict__ dst) {
    int i = blockIdx.x * blockDim.x + threadIdx.x;
    if (i < NE) atomicAdd(&g_deg[dst[i]], 1);      // edge count (deg = count+1)
    if (i < NN * FIN / 4) {
        float4 v = ((const float4*)x)[i];
        uint2 u;
        u.x = packbf(v.x, v.y);
        u.y = packbf(v.z, v.w);
        ((uint2*)g_xbf)[i] = u;
    }
}

// ---- scanA: per-block local inclusive scan of edge counts; dinv = rsqrt(count+1) ----
__global__ __launch_bounds__(256) void k_scanA() {
    int b = blockIdx.x, t = threadIdx.x;
    int base = b * SCAN_SPAN + t * 4;
    int v[4], s = 0;
    #pragma unroll
    for (int k = 0; k < 4; k++) {
        int i = base + k;
        int c = (i < NN) ? g_deg[i] : 0;           // edge count
        if (i < NN) g_dinv[i] = rsqrtf((float)(c + 1));
        v[k] = (i < NN) ? c : 0;
        s += v[k];
    }
    int lane = t & 31, wid = t >> 5;
    int x = s;
    #pragma unroll
    for (int off = 1; off < 32; off <<= 1) {
        int y = __shfl_up_sync(0xffffffffu, x, off);
        if (lane >= off) x += y;
    }
    __shared__ int ws[8];
    if (lane == 31) ws[wid] = x;
    __syncthreads();
    if (wid == 0) {
        int w = (lane < 8) ? ws[lane] : 0;
        #pragma unroll
        for (int off = 1; off < 8; off <<= 1) {
            int y = __shfl_up_sync(0xffffffffu, w, off);
            if (lane >= off) w += y;
        }
        if (lane < 8) ws[lane] = w;
    }
    __syncthreads();
    int thread_excl = x - s + (wid > 0 ? ws[wid - 1] : 0);
    int run = thread_excl;
    #pragma unroll
    for (int k = 0; k < 4; k++) {
        run += v[k];
        int i = base + k;
        if (i < NN) g_rowptr[i + 1] = run;
    }
    if (t == 255) g_bsum[b] = thread_excl + s;
}

// ---- scanC: inline prefix of g_bsum, add offsets, seed g_cur, re-zero g_deg ----
__global__ __launch_bounds__(256) void k_scanC() {
    __shared__ int sp[64];
    int b = blockIdx.x, t = threadIdx.x;
    if (t < 64) sp[t] = (t < b && t < SCAN_NB) ? g_bsum[t] : 0;
    __syncthreads();
    #pragma unroll
    for (int o = 32; o > 0; o >>= 1) {
        if (t < o) sp[t] += sp[t + o];
        __syncthreads();
    }
    int off = sp[0];
    int base = b * SCAN_SPAN + t * 4;
    #pragma unroll
    for (int k = 0; k < 4; k++) {
        int i = base + k;
        if (i < NN) {
            int rp = g_rowptr[i + 1] + off;
            g_rowptr[i + 1] = rp;
            g_cur[i + 1] = rp;
            g_deg[i] = 0;                      // restore zero-invariant for next call
        }
    }
    if (b == 0 && t == 0) { g_rowptr[0] = 0; g_cur[0] = 0; }
}

// ---- fill: counting-sort edges; 4 edges/thread, atomics batched for MLP ----
#define FILL_U 4
__global__ void k_fill(const int* __restrict__ src, const int* __restrict__ dst) {
    int base = (blockIdx.x * blockDim.x + threadIdx.x) * FILL_U;
    if (base + FILL_U <= NE) {
        int d[FILL_U], p[FILL_U], s[FILL_U];
        #pragma unroll
        for (int k = 0; k < FILL_U; k++) d[k] = dst[base + k];
        #pragma unroll
        for (int k = 0; k < FILL_U; k++) s[k] = src[base + k];
        #pragma unroll
        for (int k = 0; k < FILL_U; k++) p[k] = atomicAdd(&g_cur[d[k]], 1);
        #pragma unroll
        for (int k = 0; k < FILL_U; k++) g_col[p[k]] = s[k];
    } else {
        for (int e = base; e < NE; e++) {
            int dd = dst[e];
            int pp = atomicAdd(&g_cur[dd], 1);
            g_col[pp] = src[e];
        }
    }
}

// ---------------- SpMM (bf16 in, fp32 accumulate, bf16 out), 8-edge unroll ----------------
// out[i] = dinv[i] * ( s(i)*h[i] + sum_j s(j)*h[j] ),  s()=dinv if SCALE else 1
template <int F, int SCALE>
__global__ void k_spmm_bf(const __nv_bfloat16* __restrict__ h,
                          __nv_bfloat16* __restrict__ out) {
    const int E2 = F / 64;   // words (bf16x2) per lane: 2 (F=128) or 4 (F=256)
    const int RW = F / 2;    // row width in words
    int gw   = (blockIdx.x * blockDim.x + threadIdx.x) >> 5;
    int lane = threadIdx.x & 31;
    if (gw >= NN) return;
    int beg = g_rowptr[gw], end = g_rowptr[gw + 1];
    float di = g_dinv[gw];
    const uint32_t* hlane = (const uint32_t*)h + lane * E2;

    float ax[E2], ay[E2];
    {
        const uint32_t* p = hlane + (size_t)gw * RW;
        uint32_t w[E2];
        if (E2 == 2) { uint2 u = *(const uint2*)p; w[0] = u.x; w[1] = u.y; }
        else         { uint4 u = *(const uint4*)p; w[0] = u.x; w[1] = u.y; w[2] = u.z; w[3] = u.w; }
        float s = SCALE ? di : 1.f;
        #pragma unroll
        for (int k = 0; k < E2; k++) {
            ax[k] = bflo(w[k]) * s;
            ay[k] = bfhi(w[k]) * s;
        }
    }
    int e = beg;
    for (; e + 8 <= end; e += 8) {
        int j[8];
        float sc[8];
        uint32_t w[8][E2];
        #pragma unroll
        for (int m = 0; m < 8; m++) j[m] = g_col[e + m];
        #pragma unroll
        for (int m = 0; m < 8; m++) sc[m] = SCALE ? g_dinv[j[m]] : 1.f;
        #pragma unroll
        for (int m = 0; m < 8; m++) {
            const uint32_t* p = hlane + (size_t)j[m] * RW;
            if (E2 == 2) { uint2 u = *(const uint2*)p; w[m][0] = u.x; w[m][1] = u.y; }
            else         { uint4 u = *(const uint4*)p; w[m][0] = u.x; w[m][1] = u.y; w[m][2] = u.z; w[m][3] = u.w; }
        }
        #pragma unroll
        for (int k = 0; k < E2; k++) {
            #pragma unroll
            for (int m = 0; m < 8; m++) {
                ax[k] += bflo(w[m][k]) * sc[m];
                ay[k] += bfhi(w[m][k]) * sc[m];
            }
        }
    }
    for (; e < end; e++) {
        int j0 = g_col[e];
        float s0 = SCALE ? g_dinv[j0] : 1.f;
        const uint32_t* p0 = hlane + (size_t)j0 * RW;
        #pragma unroll
        for (int k = 0; k < E2; k++) {
            uint32_t w = p0[k];
            ax[k] += bflo(w) * s0;
            ay[k] += bfhi(w) * s0;
        }
    }
    uint32_t* op = (uint32_t*)out + (size_t)gw * RW + lane * E2;
    if (E2 == 2) {
        uint2 u;
        u.x = packbf(ax[0] * di, ay[0] * di);
        u.y = packbf(ax[1] * di, ay[1] * di);
        *(uint2*)op = u;
    } else {
        uint4 u;
        u.x = packbf(ax[0] * di, ay[0] * di);
        u.y = packbf(ax[1] * di, ay[1] * di);
        u.z = packbf(ax[2] * di, ay[2] * di);
        u.w = packbf(ax[3] * di, ay[3] * di);
        *(uint4*)op = u;
    }
}

// ---------------- bf16 tensor-core GEMM ----------------
// C[M,256] = op(A_bf16[M,K] @ B_f32[K,256] + bias)
// flags: 1=relu, 2=scale rows by g_dinv, 4=write bf16 (else fp32)
__device__ __forceinline__ void mma_bf16(float* d, const uint32_t* a, const uint32_t* b) {
    asm volatile(
        "mma.sync.aligned.m16n8k16.row.col.f32.bf16.bf16.f32 "
        "{%0,%1,%2,%3}, {%4,%5,%6,%7}, {%8,%9}, {%0,%1,%2,%3};\n"
        : "+f"(d[0]), "+f"(d[1]), "+f"(d[2]), "+f"(d[3])
        : "r"(a[0]), "r"(a[1]), "r"(a[2]), "r"(a[3]), "r"(b[0]), "r"(b[1]));
}

__global__ __launch_bounds__(256)
void k_bfgemm(const __nv_bfloat16* __restrict__ A, const float* __restrict__ B,
              const float* __restrict__ bias, void* __restrict__ C,
              int M, int K, int flags) {
    __shared__ uint32_t As[16][136];   // [k-pair][m]
    __shared__ uint32_t Bs[16][136];   // [k-pair][n]; 136*4=544B row stride, 16-divisible

    int tid  = threadIdx.x;
    int row0 = blockIdx.y * 128, col0 = blockIdx.x * 128;
    int lane = tid & 31, wid = tid >> 5;
    int wm = wid >> 2, wn = wid & 3;
    int q = lane & 3, g = lane >> 2;

    int a_row = tid & 127, a_half = tid >> 7;
    int b_kh = tid >> 4,  b_n = (tid & 15) * 8;

    float acc[4][4][4];
    #pragma unroll
    for (int mt = 0; mt < 4; mt++)
        #pragma unroll
        for (int nt = 0; nt < 4; nt++)
            #pragma unroll
            for (int c = 0; c < 4; c++) acc[mt][nt][c] = 0.f;

    uint4 aw0, aw1;
    float4 br00, br01, br10, br11;
    {
        int r = row0 + a_row;
        if (r < M) {
            const uint4* ap = (const uint4*)(A + (size_t)r * K + a_half * 16);
            aw0 = ap[0]; aw1 = ap[1];
        } else {
            aw0 = aw1 = make_uint4(0, 0, 0, 0);
        }
        int kr = 2 * b_kh;
        const float4* bp0 = (const float4*)(B + (size_t)kr * 256 + col0 + b_n);
        const float4* bp1 = (const float4*)(B + (size_t)(kr + 1) * 256 + col0 + b_n);
        br00 = bp0[0]; br01 = bp0[1];
        br10 = bp1[0]; br11 = bp1[1];
    }

    for (int k0 = 0; k0 < K; k0 += 32) {
        __syncthreads();
        {
            int kp = a_half * 8;
            As[kp + 0][a_row] = aw0.x;
            As[kp + 1][a_row] = aw0.y;
            As[kp + 2][a_row] = aw0.z;
            As[kp + 3][a_row] = aw0.w;
            As[kp + 4][a_row] = aw1.x;
            As[kp + 5][a_row] = aw1.y;
            As[kp + 6][a_row] = aw1.z;
            As[kp + 7][a_row] = aw1.w;
            uint4 bv0 = make_uint4(packbf(br00.x, br10.x), packbf(br00.y, br10.y),
                                   packbf(br00.z, br10.z), packbf(br00.w, br10.w));
            uint4 bv1 = make_uint4(packbf(br01.x, br11.x), packbf(br01.y, br11.y),
                                   packbf(br01.z, br11.z), packbf(br01.w, br11.w));
            *(uint4*)&Bs[b_kh][b_n]     = bv0;
            *(uint4*)&Bs[b_kh][b_n + 4] = bv1;
        }
        __syncthreads();

        if (k0 + 32 < K) {
            int r = row0 + a_row;
            if (r < M) {
                const uint4* ap = (const uint4*)(A + (size_t)r * K + k0 + 32 + a_half * 16);
                aw0 = ap[0]; aw1 = ap[1];
            } else {
                aw0 = aw1 = make_uint4(0, 0, 0, 0);
            }
            int kr = k0 + 32 + 2 * b_kh;
            const float4* bp0 = (const float4*)(B + (size_t)kr * 256 + col0 + b_n);
            const float4* bp1 = (const float4*)(B + (size_t)(kr + 1) * 256 + col0 + b_n);
            br00 = bp0[0]; br01 = bp0[1];
            br10 = bp1[0]; br11 = bp1[1];
        }

        #pragma unroll
        for (int kb = 0; kb < 2; kb++) {
            int p = kb * 8;
            uint32_t af[4][4], bfr[4][2];
            #pragma unroll
            for (int mt = 0; mt < 4; mt++) {
                int m = wm * 64 + mt * 16 + g;
                af[mt][0] = As[p + q][m];
                af[mt][1] = As[p + q][m + 8];
                af[mt][2] = As[p + q + 4][m];
                af[mt][3] = As[p + q + 4][m + 8];
            }
            #pragma unroll
            for (int nt = 0; nt < 4; nt++) {
                int n = wn * 32 + nt * 8 + g;
                bfr[nt][0] = Bs[p + q][n];
                bfr[nt][1] = Bs[p + q + 4][n];
            }
            #pragma unroll
            for (int mt = 0; mt < 4; mt++)
                #pragma unroll
                for (int nt = 0; nt < 4; nt++)
                    mma_bf16(acc[mt][nt], af[mt], bfr[nt]);
        }
    }

    float* Cf = (float*)C;
    __nv_bfloat16* Cb = (__nv_bfloat16*)C;
    #pragma unroll
    for (int nt = 0; nt < 4; nt++) {
        int c = col0 + wn * 32 + nt * 8 + q * 2;
        float blo = bias[c], bhi = bias[c + 1];
        #pragma unroll
        for (int half = 0; half < 2; half++) {
            #pragma unroll
            for (int mt = 0; mt < 4; mt++) {
                int r = row0 + wm * 64 + mt * 16 + g + half * 8;
                if (r < M) {
                    float sc = (flags & 2) ? g_dinv[r] : 1.f;
                    float vx = acc[mt][nt][half * 2 + 0] + blo;
                    float vy = acc[mt][nt][half * 2 + 1] + bhi;
                    if (flags & 1) { vx = fmaxf(vx, 0.f); vy = fmaxf(vy, 0.f); }
                    vx *= sc; vy *= sc;
                    if (flags & 4) {
                        *(uint32_t*)(Cb + (size_t)r * 256 + c) = packbf(vx, vy);
                    } else {
                        *(float2*)(Cf + (size_t)r * 256 + c) = make_float2(vx, vy);
                    }
                }
            }
        }
    }
}

// ---------------- pooling + classifier ----------------
__global__ void k_gs(const int* __restrict__ batch) {
    int t = threadIdx.x;
    if (t > NG) return;
    int lo = 0, hi = NN;
    while (lo < hi) {
        int mid = (lo + hi) >> 1;
        if (batch[mid] < t) lo = mid + 1; else hi = mid;
    }
    g_gs[t] = lo;
}

__global__ void k_pool() {
    int g = blockIdx.x, t = threadIdx.x;   // 256 threads, one per column
    int beg = g_gs[g], end = g_gs[g + 1];
    float s = 0.f;
    for (int n = beg; n < end; n++)
        s += __bfloat162float(g_h2[(size_t)n * HID + t]);
    float cnt = (float)(end - beg);
    g_pool[g * HID + t] = s / fmaxf(cnt, 1.f);
}

__global__ void k_cls(const float* __restrict__ W3, const float* __restrict__ b3,
                      const float* __restrict__ W4, const float* __restrict__ b4,
                      float* __restrict__ out) {
    int b = blockIdx.x, t = threadIdx.x;   // 128 threads
    __shared__ float gv[HID];
    __shared__ float red[128];
    for (int j = t; j < HID; j += 128) gv[j] = g_pool[b * HID + j];
    __syncthreads();
    float z = b3[t];
    for (int j = 0; j < HID; j++) z += gv[j] * W3[j * 128 + t];
    z = fmaxf(z, 0.f);
    red[t] = z * W4[t];
    __syncthreads();
    for (int off = 64; off > 0; off >>= 1) {
        if (t < off) red[t] += red[t + off];
        __syncthreads();
    }
    if (t == 0) out[b] = 1.f / (1.f + expf(-(red[0] + b4[0])));
}

// ---------------- launch ----------------
extern "C" void kernel_launch(void* const* d_in, const int* in_sizes, int n_in,
                              void* d_out, int out_size) {
    const float* x     = (const float*)d_in[0];
    const int*   ei    = (const int*)  d_in[1];
    const int*   batch = (const int*)  d_in[2];
    const float* W1 = (const float*)d_in[3];  const float* b1 = (const float*)d_in[4];
    const float* W2 = (const float*)d_in[5];  const float* b2 = (const float*)d_in[6];
    const float* W3 = (const float*)d_in[7];  const float* b3 = (const float*)d_in[8];
    const float* W4 = (const float*)d_in[9];  const float* b4 = (const float*)d_in[10];
    float* out = (float*)d_out;
    const int* src = ei;
    const int* dst = ei + NE;

    __nv_bfloat16 *xbf, *agg1, *h1, *agg2, *h2;
    cudaGetSymbolAddress((void**)&xbf,  g_xbf);
    cudaGetSymbolAddress((void**)&agg1, g_agg1);
    cudaGetSymbolAddress((void**)&h1,   g_h1);
    cudaGetSymbolAddress((void**)&agg2, g_agg2);
    cudaGetSymbolAddress((void**)&h2,   g_h2);

    const int TB = 256;
    const int HI = (NN * FIN / 4 > NE) ? NN * FIN / 4 : NE;   // 1.6M threads
    k_histinit<<<(HI + TB - 1) / TB, TB>>>(x, dst);
    k_scanA   <<<SCAN_NB, 256>>>();
    k_scanC   <<<SCAN_NB, 256>>>();
    k_fill    <<<(NE / FILL_U + TB - 1) / TB, TB>>>(src, dst);

    dim3 gg(2, (NN + 127) / 128);

    // layer 1: aggregate bf16 x (128), bf16 GEMM -> bf16 h1 (relu, *dinv)
    k_spmm_bf<128, 1><<<(NN * 32 + TB - 1) / TB, TB>>>(xbf, agg1);
    k_bfgemm<<<gg, TB>>>(agg1, W1, b1, h1, NN, FIN, 1 | 2 | 4);

    // layer 2: aggregate bf16 h1 (256), bf16 GEMM -> bf16 h2 (relu)
    k_spmm_bf<256, 0><<<(NN * 32 + TB - 1) / TB, TB>>>(h1, agg2);
    k_bfgemm<<<gg, TB>>>(agg2, W2, b2, h2, NN, HID, 1 | 4);

    // pool + classifier
    k_gs  <<<1, 256>>>(batch);
    k_pool<<<NG, 256>>>();
    k_cls <<<NG, 128>>>(W3, b3, W4, b4, out);
}

// round 16
// speedup vs baseline: 1.0190x; 1.0190x over previous
#include <cuda_runtime.h>
#include <cuda_bf16.h>
#include <math.h>
#include <stdint.h>

#define NN  50000
#define NE  800000
#define FIN 128
#define HID 256
#define NG  128

#define SCAN_SPAN 1024
#define SCAN_NB   ((NN + SCAN_SPAN - 1) / SCAN_SPAN)   // 49

// ---------------- scratch (static device globals; no allocation) ----------------
__device__ int   g_deg[NN];        // ZERO at entry of every call (static-zero first call;
                                   // re-zeroed by k_scanC each call after last read)
__device__ float g_dinv[NN];
__device__ int   g_rowptr[NN + 1];
__device__ int   g_cur[NN + 1];
__device__ int   g_col[NE];
__device__ int   g_bsum[SCAN_NB];
__device__ __nv_bfloat16 g_xbf [(size_t)NN * FIN];
__device__ __nv_bfloat16 g_agg1[(size_t)NN * FIN];
__device__ __nv_bfloat16 g_h1  [(size_t)NN * HID];
__device__ __nv_bfloat16 g_agg2[(size_t)NN * HID];
__device__ __nv_bfloat16 g_h2  [(size_t)NN * HID];
__device__ float g_pool[NG * HID];
__device__ int   g_gs[NG + 1];

__device__ __forceinline__ uint32_t packbf(float lo, float hi) {
    __nv_bfloat162 t = __floats2bfloat162_rn(lo, hi);
    return *reinterpret_cast<uint32_t*>(&t);
}
// exact bf16 -> f32 widening via bit ops (SHF/LOP3, lat 4, alu pipe; no CVT)
__device__ __forceinline__ float bflo(uint32_t u) { return __int_as_float(u << 16); }
__device__ __forceinline__ float bfhi(uint32_t u) { return __int_as_float(u & 0xFFFF0000u); }

// ---------------- fused: edge histogram (into zeroed g_deg) + x->bf16 ----------------
__global__ void k_histinit(const float* __restrict__ x, const int* __restrict__ dst) {
    int i = blockIdx.x * blockDim.x + threadIdx.x;
    if (i < NE) atomicAdd(&g_deg[dst[i]], 1);      // edge count (deg = count+1)
    if (i < NN * FIN / 4) {
        float4 v = ((const float4*)x)[i];
        uint2 u;
        u.x = packbf(v.x, v.y);
        u.y = packbf(v.z, v.w);
        ((uint2*)g_xbf)[i] = u;
    }
}

// ---- scanA: per-block local inclusive scan of edge counts; dinv = rsqrt(count+1) ----
__global__ __launch_bounds__(256) void k_scanA() {
    int b = blockIdx.x, t = threadIdx.x;
    int base = b * SCAN_SPAN + t * 4;
    int v[4], s = 0;
    #pragma unroll
    for (int k = 0; k < 4; k++) {
        int i = base + k;
        int c = (i < NN) ? g_deg[i] : 0;           // edge count
        if (i < NN) g_dinv[i] = rsqrtf((float)(c + 1));
        v[k] = (i < NN) ? c : 0;
        s += v[k];
    }
    int lane = t & 31, wid = t >> 5;
    int x = s;
    #pragma unroll
    for (int off = 1; off < 32; off <<= 1) {
        int y = __shfl_up_sync(0xffffffffu, x, off);
        if (lane >= off) x += y;
    }
    __shared__ int ws[8];
    if (lane == 31) ws[wid] = x;
    __syncthreads();
    if (wid == 0) {
        int w = (lane < 8) ? ws[lane] : 0;
        #pragma unroll
        for (int off = 1; off < 8; off <<= 1) {
            int y = __shfl_up_sync(0xffffffffu, w, off);
            if (lane >= off) w += y;
        }
        if (lane < 8) ws[lane] = w;
    }
    __syncthreads();
    int thread_excl = x - s + (wid > 0 ? ws[wid - 1] : 0);
    int run = thread_excl;
    #pragma unroll
    for (int k = 0; k < 4; k++) {
        run += v[k];
        int i = base + k;
        if (i < NN) g_rowptr[i + 1] = run;
    }
    if (t == 255) g_bsum[b] = thread_excl + s;
}

// ---- scanC: inline prefix of g_bsum, add offsets, seed g_cur, re-zero g_deg.
//      Extra block (b == SCAN_NB) computes graph segment starts (independent input).
__global__ __launch_bounds__(256) void k_scanC(const int* __restrict__ batch) {
    __shared__ int sp[64];
    int b = blockIdx.x, t = threadIdx.x;

    if (b == SCAN_NB) {                      // folded k_gs: 129 binary searches
        if (t <= NG) {
            int lo = 0, hi = NN;
            while (lo < hi) {
                int mid = (lo + hi) >> 1;
                if (batch[mid] < t) lo = mid + 1; else hi = mid;
            }
            g_gs[t] = lo;
        }
        return;
    }

    if (t < 64) sp[t] = (t < b && t < SCAN_NB) ? g_bsum[t] : 0;
    __syncthreads();
    #pragma unroll
    for (int o = 32; o > 0; o >>= 1) {
        if (t < o) sp[t] += sp[t + o];
        __syncthreads();
    }
    int off = sp[0];
    int base = b * SCAN_SPAN + t * 4;
    #pragma unroll
    for (int k = 0; k < 4; k++) {
        int i = base + k;
        if (i < NN) {
            int rp = g_rowptr[i + 1] + off;
            g_rowptr[i + 1] = rp;
            g_cur[i + 1] = rp;
            g_deg[i] = 0;                      // restore zero-invariant for next call
        }
    }
    if (b == 0 && t == 0) { g_rowptr[0] = 0; g_cur[0] = 0; }
}

// ---- fill: counting-sort edges by dst (1 edge/thread; at L2-atomic floor) ----
__global__ void k_fill(const int* __restrict__ src, const int* __restrict__ dst) {
    int e = blockIdx.x * blockDim.x + threadIdx.x;
    if (e < NE) {
        int d = dst[e];
        int p = atomicAdd(&g_cur[d], 1);
        g_col[p] = src[e];
    }
}

// ---------------- SpMM (bf16 in, fp32 accumulate, bf16 out), 8-edge unroll ----------------
// out[i] = dinv[i] * ( s(i)*h[i] + sum_j s(j)*h[j] ),  s()=dinv if SCALE else 1
template <int F, int SCALE>
__global__ void k_spmm_bf(const __nv_bfloat16* __restrict__ h,
                          __nv_bfloat16* __restrict__ out) {
    const int E2 = F / 64;   // words (bf16x2) per lane: 2 (F=128) or 4 (F=256)
    const int RW = F / 2;    // row width in words
    int gw   = (blockIdx.x * blockDim.x + threadIdx.x) >> 5;
    int lane = threadIdx.x & 31;
    if (gw >= NN) return;
    int beg = g_rowptr[gw], end = g_rowptr[gw + 1];
    float di = g_dinv[gw];
    const uint32_t* hlane = (const uint32_t*)h + lane * E2;

    float ax[E2], ay[E2];
    {
        const uint32_t* p = hlane + (size_t)gw * RW;
        uint32_t w[E2];
        if (E2 == 2) { uint2 u = *(const uint2*)p; w[0] = u.x; w[1] = u.y; }
        else         { uint4 u = *(const uint4*)p; w[0] = u.x; w[1] = u.y; w[2] = u.z; w[3] = u.w; }
        float s = SCALE ? di : 1.f;
        #pragma unroll
        for (int k = 0; k < E2; k++) {
            ax[k] = bflo(w[k]) * s;
            ay[k] = bfhi(w[k]) * s;
        }
    }
    int e = beg;
    for (; e + 8 <= end; e += 8) {
        int j[8];
        float sc[8];
        uint32_t w[8][E2];
        #pragma unroll
        for (int m = 0; m < 8; m++) j[m] = g_col[e + m];
        #pragma unroll
        for (int m = 0; m < 8; m++) sc[m] = SCALE ? g_dinv[j[m]] : 1.f;
        #pragma unroll
        for (int m = 0; m < 8; m++) {
            const uint32_t* p = hlane + (size_t)j[m] * RW;
            if (E2 == 2) { uint2 u = *(const uint2*)p; w[m][0] = u.x; w[m][1] = u.y; }
            else         { uint4 u = *(const uint4*)p; w[m][0] = u.x; w[m][1] = u.y; w[m][2] = u.z; w[m][3] = u.w; }
        }
        #pragma unroll
        for (int k = 0; k < E2; k++) {
            #pragma unroll
            for (int m = 0; m < 8; m++) {
                ax[k] += bflo(w[m][k]) * sc[m];
                ay[k] += bfhi(w[m][k]) * sc[m];
            }
        }
    }
    for (; e < end; e++) {
        int j0 = g_col[e];
        float s0 = SCALE ? g_dinv[j0] : 1.f;
        const uint32_t* p0 = hlane + (size_t)j0 * RW;
        #pragma unroll
        for (int k = 0; k < E2; k++) {
            uint32_t w = p0[k];
            ax[k] += bflo(w) * s0;
            ay[k] += bfhi(w) * s0;
        }
    }
    uint32_t* op = (uint32_t*)out + (size_t)gw * RW + lane * E2;
    if (E2 == 2) {
        uint2 u;
        u.x = packbf(ax[0] * di, ay[0] * di);
        u.y = packbf(ax[1] * di, ay[1] * di);
        *(uint2*)op = u;
    } else {
        uint4 u;
        u.x = packbf(ax[0] * di, ay[0] * di);
        u.y = packbf(ax[1] * di, ay[1] * di);
        u.z = packbf(ax[2] * di, ay[2] * di);
        u.w = packbf(ax[3] * di, ay[3] * di);
        *(uint4*)op = u;
    }
}

// ---------------- bf16 tensor-core GEMM ----------------
// C[M,256] = op(A_bf16[M,K] @ B_f32[K,256] + bias)
// flags: 1=relu, 2=scale rows by g_dinv, 4=write bf16 (else fp32)
__device__ __forceinline__ void mma_bf16(float* d, const uint32_t* a, const uint32_t* b) {
    asm volatile(
        "mma.sync.aligned.m16n8k16.row.col.f32.bf16.bf16.f32 "
        "{%0,%1,%2,%3}, {%4,%5,%6,%7}, {%8,%9}, {%0,%1,%2,%3};\n"
        : "+f"(d[0]), "+f"(d[1]), "+f"(d[2]), "+f"(d[3])
        : "r"(a[0]), "r"(a[1]), "r"(a[2]), "r"(a[3]), "r"(b[0]), "r"(b[1]));
}

__global__ __launch_bounds__(256)
void k_bfgemm(const __nv_bfloat16* __restrict__ A, const float* __restrict__ B,
              const float* __restrict__ bias, void* __restrict__ C,
              int M, int K, int flags) {
    __shared__ uint32_t As[16][136];   // [k-pair][m]
    __shared__ uint32_t Bs[16][136];   // [k-pair][n]; 136*4=544B row stride, 16-divisible

    int tid  = threadIdx.x;
    int row0 = blockIdx.y * 128, col0 = blockIdx.x * 128;
    int lane = tid & 31, wid = tid >> 5;
    int wm = wid >> 2, wn = wid & 3;
    int q = lane & 3, g = lane >> 2;

    int a_row = tid & 127, a_half = tid >> 7;
    int b_kh = tid >> 4,  b_n = (tid & 15) * 8;

    float acc[4][4][4];
    #pragma unroll
    for (int mt = 0; mt < 4; mt++)
        #pragma unroll
        for (int nt = 0; nt < 4; nt++)
            #pragma unroll
            for (int c = 0; c < 4; c++) acc[mt][nt][c] = 0.f;

    uint4 aw0, aw1;
    float4 br00, br01, br10, br11;
    {
        int r = row0 + a_row;
        if (r < M) {
            const uint4* ap = (const uint4*)(A + (size_t)r * K + a_half * 16);
            aw0 = ap[0]; aw1 = ap[1];
        } else {
            aw0 = aw1 = make_uint4(0, 0, 0, 0);
        }
        int kr = 2 * b_kh;
        const float4* bp0 = (const float4*)(B + (size_t)kr * 256 + col0 + b_n);
        const float4* bp1 = (const float4*)(B + (size_t)(kr + 1) * 256 + col0 + b_n);
        br00 = bp0[0]; br01 = bp0[1];
        br10 = bp1[0]; br11 = bp1[1];
    }

    for (int k0 = 0; k0 < K; k0 += 32) {
        __syncthreads();
        {
            int kp = a_half * 8;
            As[kp + 0][a_row] = aw0.x;
            As[kp + 1][a_row] = aw0.y;
            As[kp + 2][a_row] = aw0.z;
            As[kp + 3][a_row] = aw0.w;
            As[kp + 4][a_row] = aw1.x;
            As[kp + 5][a_row] = aw1.y;
            As[kp + 6][a_row] = aw1.z;
            As[kp + 7][a_row] = aw1.w;
            uint4 bv0 = make_uint4(packbf(br00.x, br10.x), packbf(br00.y, br10.y),
                                   packbf(br00.z, br10.z), packbf(br00.w, br10.w));
            uint4 bv1 = make_uint4(packbf(br01.x, br11.x), packbf(br01.y, br11.y),
                                   packbf(br01.z, br11.z), packbf(br01.w, br11.w));
            *(uint4*)&Bs[b_kh][b_n]     = bv0;
            *(uint4*)&Bs[b_kh][b_n + 4] = bv1;
        }
        __syncthreads();

        if (k0 + 32 < K) {
            int r = row0 + a_row;
            if (r < M) {
                const uint4* ap = (const uint4*)(A + (size_t)r * K + k0 + 32 + a_half * 16);
                aw0 = ap[0]; aw1 = ap[1];
            } else {
                aw0 = aw1 = make_uint4(0, 0, 0, 0);
            }
            int kr = k0 + 32 + 2 * b_kh;
            const float4* bp0 = (const float4*)(B + (size_t)kr * 256 + col0 + b_n);
            const float4* bp1 = (const float4*)(B + (size_t)(kr + 1) * 256 + col0 + b_n);
            br00 = bp0[0]; br01 = bp0[1];
            br10 = bp1[0]; br11 = bp1[1];
        }

        #pragma unroll
        for (int kb = 0; kb < 2; kb++) {
            int p = kb * 8;
            uint32_t af[4][4], bfr[4][2];
            #pragma unroll
            for (int mt = 0; mt < 4; mt++) {
                int m = wm * 64 + mt * 16 + g;
                af[mt][0] = As[p + q][m];
                af[mt][1] = As[p + q][m + 8];
                af[mt][2] = As[p + q + 4][m];
                af[mt][3] = As[p + q + 4][m + 8];
            }
            #pragma unroll
            for (int nt = 0; nt < 4; nt++) {
                int n = wn * 32 + nt * 8 + g;
                bfr[nt][0] = Bs[p + q][n];
                bfr[nt][1] = Bs[p + q + 4][n];
            }
            #pragma unroll
            for (int mt = 0; mt < 4; mt++)
                #pragma unroll
                for (int nt = 0; nt < 4; nt++)
                    mma_bf16(acc[mt][nt], af[mt], bfr[nt]);
        }
    }

    float* Cf = (float*)C;
    __nv_bfloat16* Cb = (__nv_bfloat16*)C;
    #pragma unroll
    for (int nt = 0; nt < 4; nt++) {
        int c = col0 + wn * 32 + nt * 8 + q * 2;
        float blo = bias[c], bhi = bias[c + 1];
        #pragma unroll
        for (int half = 0; half < 2; half++) {
            #pragma unroll
            for (int mt = 0; mt < 4; mt++) {
                int r = row0 + wm * 64 + mt * 16 + g + half * 8;
                if (r < M) {
                    float sc = (flags & 2) ? g_dinv[r] : 1.f;
                    float vx = acc[mt][nt][half * 2 + 0] + blo;
                    float vy = acc[mt][nt][half * 2 + 1] + bhi;
                    if (flags & 1) { vx = fmaxf(vx, 0.f); vy = fmaxf(vy, 0.f); }
                    vx *= sc; vy *= sc;
                    if (flags & 4) {
                        *(uint32_t*)(Cb + (size_t)r * 256 + c) = packbf(vx, vy);
                    } else {
                        *(float2*)(Cf + (size_t)r * 256 + c) = make_float2(vx, vy);
                    }
                }
            }
        }
    }
}

// ---------------- pooling + classifier ----------------
__global__ void k_pool() {
    int g = blockIdx.x, t = threadIdx.x;   // 256 threads, one per column
    int beg = g_gs[g], end = g_gs[g + 1];
    float s = 0.f;
    for (int n = beg; n < end; n++)
        s += __bfloat162float(g_h2[(size_t)n * HID + t]);
    float cnt = (float)(end - beg);
    g_pool[g * HID + t] = s / fmaxf(cnt, 1.f);
}

__global__ void k_cls(const float* __restrict__ W3, const float* __restrict__ b3,
                      const float* __restrict__ W4, const float* __restrict__ b4,
                      float* __restrict__ out) {
    int b = blockIdx.x, t = threadIdx.x;   // 128 threads
    __shared__ float gv[HID];
    __shared__ float red[128];
    for (int j = t; j < HID; j += 128) gv[j] = g_pool[b * HID + j];
    __syncthreads();
    float z = b3[t];
    for (int j = 0; j < HID; j++) z += gv[j] * W3[j * 128 + t];
    z = fmaxf(z, 0.f);
    red[t] = z * W4[t];
    __syncthreads();
    for (int off = 64; off > 0; off >>= 1) {
        if (t < off) red[t] += red[t + off];
        __syncthreads();
    }
    if (t == 0) out[b] = 1.f / (1.f + expf(-(red[0] + b4[0])));
}

// ---------------- launch ----------------
extern "C" void kernel_launch(void* const* d_in, const int* in_sizes, int n_in,
                              void* d_out, int out_size) {
    const float* x     = (const float*)d_in[0];
    const int*   ei    = (const int*)  d_in[1];
    const int*   batch = (const int*)  d_in[2];
    const float* W1 = (const float*)d_in[3];  const float* b1 = (const float*)d_in[4];
    const float* W2 = (const float*)d_in[5];  const float* b2 = (const float*)d_in[6];
    const float* W3 = (const float*)d_in[7];  const float* b3 = (const float*)d_in[8];
    const float* W4 = (const float*)d_in[9];  const float* b4 = (const float*)d_in[10];
    float* out = (float*)d_out;
    const int* src = ei;
    const int* dst = ei + NE;

    __nv_bfloat16 *xbf, *agg1, *h1, *agg2, *h2;
    cudaGetSymbolAddress((void**)&xbf,  g_xbf);
    cudaGetSymbolAddress((void**)&agg1, g_agg1);
    cudaGetSymbolAddress((void**)&h1,   g_h1);
    cudaGetSymbolAddress((void**)&agg2, g_agg2);
    cudaGetSymbolAddress((void**)&h2,   g_h2);

    const int TB = 256;
    const int HI = (NN * FIN / 4 > NE) ? NN * FIN / 4 : NE;   // 1.6M threads
    k_histinit<<<(HI + TB - 1) / TB, TB>>>(x, dst);
    k_scanA   <<<SCAN_NB, 256>>>();
    k_scanC   <<<SCAN_NB + 1, 256>>>(batch);     // +1 block computes g_gs
    k_fill    <<<(NE + TB - 1) / TB, TB>>>(src, dst);

    dim3 gg(2, (NN + 127) / 128);

    // layer 1: aggregate bf16 x (128), bf16 GEMM -> bf16 h1 (relu, *dinv)
    k_spmm_bf<128, 1><<<(NN * 32 + TB - 1) / TB, TB>>>(xbf, agg1);
    k_bfgemm<<<gg, TB>>>(agg1, W1, b1, h1, NN, FIN, 1 | 2 | 4);

    // layer 2: aggregate bf16 h1 (256), bf16 GEMM -> bf16 h2 (relu)
    k_spmm_bf<256, 0><<<(NN * 32 + TB - 1) / TB, TB>>>(h1, agg2);
    k_bfgemm<<<gg, TB>>>(agg2, W2, b2, h2, NN, HID, 1 | 4);

    // pool + classifier
    k_pool<<<NG, 256>>>();
    k_cls <<<NG, 128>>>(W3, b3, W4, b4, out);
}